// round 2
// baseline (speedup 1.0000x reference)
#include <cuda_runtime.h>

#define C   256
#define A   512
#define NS  128

// ---- scratch (device globals; no allocations allowed) ----
__device__ float g_ave_s[C * A];
__device__ float g_ave_t[C * A];
__device__ float g_icnt_s[C];      // 1 / max(count_s, 1)
__device__ float g_P[NS * C];      // P[m,c] = (s_m - ave_s[ts_m]) . W[c]
__device__ float g_Y[NS * C];      // Y[n,c] = aug_n . W[c] + bias[c]

// ============================================================
// K1: per-class means for s and t.  Also zeroes d_out.
// grid = 2*C blocks (low 8 bits = class, bit 8 = which tensor), 128 threads.
// Each thread owns 4 contiguous dims via float4.
// Empty classes get ave = 0 automatically (sum = 0, icnt = 1).
// ============================================================
__global__ void stats_kernel(const float* __restrict__ s_feat,
                             const float* __restrict__ t_feat,
                             const int* __restrict__ ts,
                             const int* __restrict__ tt,
                             float* __restrict__ out) {
    const int bid   = blockIdx.x;
    const int c     = bid & (C - 1);
    const int which = bid >> 8;
    const float* feat = which ? t_feat : s_feat;
    const int*   lbl  = which ? tt     : ts;

    if (bid == 0 && threadIdx.x == 0) *out = 0.0f;

    __shared__ int sl[NS];
    const int tid = threadIdx.x;          // 128 threads
    if (tid < NS) sl[tid] = lbl[tid];
    __syncthreads();

    float4 sum = make_float4(0.f, 0.f, 0.f, 0.f);
    int cnt = 0;
    for (int n = 0; n < NS; n++) {
        if (sl[n] == c) {
            cnt++;
            const float4 v = *reinterpret_cast<const float4*>(feat + n * A + tid * 4);
            sum.x += v.x; sum.y += v.y; sum.z += v.z; sum.w += v.w;
        }
    }
    const float icnt = 1.0f / (float)(cnt > 0 ? cnt : 1);
    float* dst = which ? g_ave_t : g_ave_s;
    float4 o = make_float4(sum.x * icnt, sum.y * icnt, sum.z * icnt, sum.w * icnt);
    *reinterpret_cast<float4*>(dst + c * A + tid * 4) = o;
    if (which == 0 && tid == 0) g_icnt_s[c] = icnt;
}

// ============================================================
// K2 (fused GEMV): for a pair of samples (m0, m0+1) and one half of the
// columns, compute BOTH
//   P[m,c] = (s_m - ave_s[ts_m]) . W[c]
//   Y[m,c] = aug_m . W[c] + bias[c],   aug_m = 0.5*(Ave[tt_m] + tAve[tt_m])
// from a single read of each W row (4 FMAs per loaded weight).
// grid = 128 blocks = 64 sample-pairs x 2 column-halves, 256 threads (8 warps).
// Each lane register-caches its 16 values of z0,z1,g0,g1 (A=512 = 32 lanes x16).
// Warp w handles columns c = half*128 + w, step 8 (coalesced W reads).
// ============================================================
__global__ void gemv_kernel(const float* __restrict__ s_feat,
                            const float* __restrict__ W,
                            const float* __restrict__ bias,
                            const int* __restrict__ ts,
                            const int* __restrict__ tt) {
    const int pair = blockIdx.x >> 1;
    const int half = blockIdx.x & 1;
    const int m0   = pair * 2;
    const int tid  = threadIdx.x;
    const int w    = tid >> 5;
    const int lane = tid & 31;

    const int cls0 = ts[m0 + 0];
    const int cls1 = ts[m0 + 1];
    const int t0   = tt[m0 + 0];
    const int t1   = tt[m0 + 1];

    float z0[16], z1[16], g0[16], g1[16];
#pragma unroll
    for (int k = 0; k < 16; k++) {
        const int a = lane + 32 * k;
        z0[k] = s_feat[(m0 + 0) * A + a] - g_ave_s[cls0 * A + a];
        z1[k] = s_feat[(m0 + 1) * A + a] - g_ave_s[cls1 * A + a];
        g0[k] = 0.5f * (g_ave_s[t0 * A + a] + g_ave_t[t0 * A + a]);
        g1[k] = 0.5f * (g_ave_s[t1 * A + a] + g_ave_t[t1 * A + a]);
    }

    const int cend = half * 128 + 128;
    for (int c = half * 128 + w; c < cend; c += 8) {
        const float* __restrict__ Wr = W + c * A;
        float a0 = 0.f, a1 = 0.f, b0 = 0.f, b1 = 0.f;
#pragma unroll
        for (int k = 0; k < 16; k++) {
            const float wv = Wr[lane + 32 * k];
            a0 = fmaf(wv, z0[k], a0);
            a1 = fmaf(wv, z1[k], a1);
            b0 = fmaf(wv, g0[k], b0);
            b1 = fmaf(wv, g1[k], b1);
        }
#pragma unroll
        for (int off = 16; off; off >>= 1) {
            a0 += __shfl_down_sync(0xffffffffu, a0, off);
            a1 += __shfl_down_sync(0xffffffffu, a1, off);
            b0 += __shfl_down_sync(0xffffffffu, b0, off);
            b1 += __shfl_down_sync(0xffffffffu, b1, off);
        }
        if (lane == 0) {
            g_P[(m0 + 0) * C + c] = a0;
            g_P[(m0 + 1) * C + c] = a1;
            const float bb = bias[c];
            g_Y[(m0 + 0) * C + c] = b0 + bb;
            g_Y[(m0 + 1) * C + c] = b1 + bb;
        }
    }
}

// ============================================================
// K3: per-sample sigma + softmax + loss.
// grid = 64 blocks (2 samples each), 256 threads (thread tid == column c).
//   x[n,c]   = Y[n,c] + 0.25 * icnt_s[t] * sum_{m: ts_m = t}(P[m,c]-P[m,t])^2,
//              t = tt_n
//   loss    += (lse(x[n,:]) - x[n,t]) / NS     (atomicAdd into d_out)
// ============================================================
__global__ void loss_kernel(const int* __restrict__ ts,
                            const int* __restrict__ ttg,
                            float* __restrict__ out) {
    __shared__ float xv[2][C];
    __shared__ int   sl[NS];
    __shared__ int   tts[2];
    __shared__ float red[8];
    __shared__ float bc;

    const int tid  = threadIdx.x;      // 256 threads
    const int n0   = blockIdx.x * 2;
    const int w    = tid >> 5;
    const int lane = tid & 31;

    if (tid < NS) sl[tid] = ts[tid];
    if (tid < 2)  tts[tid] = ttg[n0 + tid];
    __syncthreads();

    // sigma term + logits: thread tid == column c
    {
        const int c = tid;
#pragma unroll
        for (int r = 0; r < 2; r++) {
            const int t = tts[r];
            float sig = 0.f;
            for (int m = 0; m < NS; m++) {
                if (sl[m] == t) {
                    const float ptt = g_P[m * C + t];   // same addr across warp -> broadcast
                    const float d   = g_P[m * C + c] - ptt;
                    sig = fmaf(d, d, sig);
                }
            }
            xv[r][c] = g_Y[(n0 + r) * C + c] + 0.25f * g_icnt_s[t] * sig;
        }
    }
    __syncthreads();

    // softmax + loss contribution per row
    float block_sum = 0.f;   // meaningful on tid 0 only
#pragma unroll
    for (int r = 0; r < 2; r++) {
        const float v = xv[r][tid];

        // block max
        float m = v;
#pragma unroll
        for (int off = 16; off; off >>= 1) m = fmaxf(m, __shfl_xor_sync(0xffffffffu, m, off));
        if (lane == 0) red[w] = m;
        __syncthreads();
        if (tid < 8) {
            float mm = red[tid];
#pragma unroll
            for (int off = 4; off; off >>= 1) mm = fmaxf(mm, __shfl_xor_sync(0xffu, mm, off));
            if (tid == 0) bc = mm;
        }
        __syncthreads();
        const float mx = bc;

        // block sum of exp
        float e = expf(v - mx);
#pragma unroll
        for (int off = 16; off; off >>= 1) e += __shfl_xor_sync(0xffffffffu, e, off);
        if (lane == 0) red[w] = e;
        __syncthreads();
        if (tid < 8) {
            float ss = red[tid];
#pragma unroll
            for (int off = 4; off; off >>= 1) ss += __shfl_xor_sync(0xffu, ss, off);
            if (tid == 0) bc = ss;
        }
        __syncthreads();

        if (tid == 0) {
            const float lse = mx + logf(bc);
            block_sum += lse - xv[r][tts[r]];
        }
        __syncthreads();   // bc/red reused next r
    }

    if (tid == 0) atomicAdd(out, block_sum * (1.0f / (float)NS));
}

// ============================================================
// launch
// inputs (metadata order): fc_weight(2C*A), fc_bias(2C), s_features(NS*A),
//                          t_features(NS*A), target_s(NS), target_t(NS)
// output: float scalar
// ============================================================
extern "C" void kernel_launch(void* const* d_in, const int* in_sizes, int n_in,
                              void* d_out, int out_size) {
    const float* fw = (const float*)d_in[0];
    const float* fb = (const float*)d_in[1];
    const float* sf = (const float*)d_in[2];
    const float* tf = (const float*)d_in[3];
    const int*   ts = (const int*)d_in[4];
    const int*   tt = (const int*)d_in[5];
    float* out = (float*)d_out;

    stats_kernel<<<2 * C, 128>>>(sf, tf, ts, tt, out);
    gemv_kernel<<<NS, 256>>>(sf, fw, fb, ts, tt);
    loss_kernel<<<NS / 2, 256>>>(ts, tt, out);
}

// round 3
// speedup vs baseline: 1.6091x; 1.6091x over previous
#include <cuda_runtime.h>

#define C   256
#define A   512
#define NS  128
#define RG  8     // rows per GEMM block
// cols per GEMM block = 64 (4 col-groups)

// ---- scratch (device globals; no allocations allowed) ----
// Q[m,c] = x_m . W[c],  m in [0,256): rows 0..127 = s_features, 128..255 = t_features
__device__ float g_Q[2 * NS * C];

__device__ __forceinline__ void fma2(unsigned long long& d,
                                     unsigned long long a,
                                     unsigned long long b) {
    asm("fma.rn.f32x2 %0, %1, %2, %0;" : "+l"(d) : "l"(a), "l"(b));
}

__device__ __forceinline__ float sum2(unsigned long long a) {
    float lo, hi;
    asm("mov.b64 {%0,%1}, %2;" : "=f"(lo), "=f"(hi) : "l"(a));
    return lo + hi;
}

// ============================================================
// K1: Q = [S;T] @ W[:C]^T   (M=256, N=256, K=512), fp32 via packed f32x2.
// grid = 32 row-groups x 4 col-groups = 128 blocks, 256 threads (8 warps).
// Each lane register-caches its K-chunk (16 floats = 8 f32x2) of 8 X rows.
// Warp w computes 8 columns; W row loads are coalesced 128-bit; result via
// shuffle reduce. Also zeroes d_out for K2's atomic accumulation.
// ============================================================
__global__ __launch_bounds__(256, 1)
void gemm_kernel(const float* __restrict__ sf,
                 const float* __restrict__ tf,
                 const float* __restrict__ W,
                 float* __restrict__ out) {
    if (blockIdx.x == 0 && threadIdx.x == 0) *out = 0.0f;

    const int rg   = blockIdx.x >> 2;   // 0..31
    const int cg   = blockIdx.x & 3;    // 0..3
    const int tid  = threadIdx.x;
    const int w    = tid >> 5;
    const int lane = tid & 31;
    const int row0 = rg * RG;

    // cache 8 rows: lane's floats are k = seg*128 + lane*4 + {0..3}, seg 0..3
    unsigned long long x2[RG][8];
#pragma unroll
    for (int r = 0; r < RG; r++) {
        const int row = row0 + r;
        const float* xr = (row < NS) ? (sf + row * A) : (tf + (row - NS) * A);
        const ulonglong2* xu = reinterpret_cast<const ulonglong2*>(xr);
#pragma unroll
        for (int seg = 0; seg < 4; seg++) {
            const ulonglong2 v = xu[seg * 32 + lane];
            x2[r][2 * seg + 0] = v.x;
            x2[r][2 * seg + 1] = v.y;
        }
    }

#pragma unroll
    for (int i = 0; i < 8; i++) {
        const int c = cg * 64 + w * 8 + i;
        const ulonglong2* wr = reinterpret_cast<const ulonglong2*>(W + c * A);

        unsigned long long acc[RG];
#pragma unroll
        for (int r = 0; r < RG; r++) acc[r] = 0ull;

#pragma unroll
        for (int seg = 0; seg < 4; seg++) {
            const ulonglong2 wv = wr[seg * 32 + lane];
#pragma unroll
            for (int r = 0; r < RG; r++) {
                fma2(acc[r], x2[r][2 * seg + 0], wv.x);
                fma2(acc[r], x2[r][2 * seg + 1], wv.y);
            }
        }

#pragma unroll
        for (int r = 0; r < RG; r++) {
            float s = sum2(acc[r]);
#pragma unroll
            for (int off = 16; off; off >>= 1)
                s += __shfl_down_sync(0xffffffffu, s, off);
            if (lane == 0) g_Q[(row0 + r) * C + c] = s;
        }
    }
}

// ============================================================
// K2: per-sample everything (class agg + sigma + softmax + loss).
// grid = 128 blocks (one per sample n), 256 threads (thread tid == column c).
// With t = tt[n], d_mc = Qs[m,c]-Qs[m,t] over members m of class t in ts:
//   sigma[n,c] = icnt * sum(d^2) - (icnt * sum(d))^2
//   x[n,c]     = 0.5*(Us[t,c] + Ut[t,c]) + bias[c] + 0.25 * sigma[n,c]
//   loss      += (lse(x) - x[t]) / NS    (atomicAdd into d_out)
// ============================================================
__global__ __launch_bounds__(256, 4)
void loss_kernel(const float* __restrict__ bias,
                 const int* __restrict__ ts,
                 const int* __restrict__ ttg,
                 float* __restrict__ out) {
    __shared__ int   sls[NS];
    __shared__ int   slt[NS];
    __shared__ float xv[C];
    __shared__ float red[8];
    __shared__ float bc;

    const int tid  = threadIdx.x;   // == column c
    const int n    = blockIdx.x;
    const int w    = tid >> 5;
    const int lane = tid & 31;

    if (tid < NS) {
        sls[tid] = ts[tid];
        slt[tid] = ttg[tid];
    }
    __syncthreads();

    const int t = slt[n];

    // pass 1: members of class t in ts  (Qs rows 0..127)
    float sig = 0.f, sd = 0.f, qs = 0.f;
    int cs = 0;
#pragma unroll 4
    for (int m = 0; m < NS; m++) {
        if (sls[m] == t) {
            const float qmt = g_Q[m * C + t];     // uniform -> broadcast
            const float qmc = g_Q[m * C + tid];   // coalesced
            const float d   = qmc - qmt;
            sig = fmaf(d, d, sig);
            sd += d;
            qs += qmc;
            cs++;
        }
    }
    const float icnt = 1.0f / (float)(cs > 0 ? cs : 1);
    const float e    = icnt * sd;
    const float sigma = icnt * sig - e * e;
    const float Us    = icnt * qs;

    // pass 2: members of class t in tt  (Qt rows 128..255)
    float qt = 0.f;
    int ct = 0;
#pragma unroll 4
    for (int m = 0; m < NS; m++) {
        if (slt[m] == t) {
            qt += g_Q[(NS + m) * C + tid];
            ct++;
        }
    }
    const float Ut = qt / (float)(ct > 0 ? ct : 1);

    const float x = 0.5f * (Us + Ut) + bias[tid] + 0.25f * sigma;
    xv[tid] = x;
    __syncthreads();

    // block max
    float mx = x;
#pragma unroll
    for (int off = 16; off; off >>= 1)
        mx = fmaxf(mx, __shfl_xor_sync(0xffffffffu, mx, off));
    if (lane == 0) red[w] = mx;
    __syncthreads();
    if (tid < 8) {
        float mm = red[tid];
#pragma unroll
        for (int off = 4; off; off >>= 1)
            mm = fmaxf(mm, __shfl_xor_sync(0xffu, mm, off));
        if (tid == 0) bc = mm;
    }
    __syncthreads();
    const float bmax = bc;

    // block sum of exp
    float es = __expf(x - bmax);
#pragma unroll
    for (int off = 16; off; off >>= 1)
        es += __shfl_xor_sync(0xffffffffu, es, off);
    if (lane == 0) red[w] = es;
    __syncthreads();
    if (tid < 8) {
        float ss = red[tid];
#pragma unroll
        for (int off = 4; off; off >>= 1)
            ss += __shfl_xor_sync(0xffu, ss, off);
        if (tid == 0) bc = ss;
    }
    __syncthreads();

    if (tid == 0) {
        const float lse = bmax + __logf(bc);
        atomicAdd(out, (lse - xv[t]) * (1.0f / (float)NS));
    }
}

// ============================================================
// launch
// inputs (metadata order): fc_weight(2C*A), fc_bias(2C), s_features(NS*A),
//                          t_features(NS*A), target_s(NS), target_t(NS)
// output: float scalar
// ============================================================
extern "C" void kernel_launch(void* const* d_in, const int* in_sizes, int n_in,
                              void* d_out, int out_size) {
    const float* fw = (const float*)d_in[0];
    const float* fb = (const float*)d_in[1];
    const float* sf = (const float*)d_in[2];
    const float* tf = (const float*)d_in[3];
    const int*   ts = (const int*)d_in[4];
    const int*   tt = (const int*)d_in[5];
    float* out = (float*)d_out;

    gemm_kernel<<<128, 256>>>(sf, tf, fw, out);
    loss_kernel<<<NS, 256>>>(fb, ts, tt, out);
}

// round 4
// speedup vs baseline: 2.0784x; 1.2917x over previous
#include <cuda_runtime.h>

#define C   256
#define A   512
#define NS  128
#define RG  8     // rows per GEMM block

// ---- scratch (device globals; no allocations allowed) ----
// Q[m,c] = x_m . W[c],  m in [0,256): rows 0..127 = s_features, 128..255 = t_features
__device__ float g_Q[2 * NS * C];

__device__ __forceinline__ void fma2(unsigned long long& d,
                                     unsigned long long a,
                                     unsigned long long b) {
    asm("fma.rn.f32x2 %0, %1, %2, %0;" : "+l"(d) : "l"(a), "l"(b));
}

__device__ __forceinline__ float sum2(unsigned long long a) {
    float lo, hi;
    asm("mov.b64 {%0,%1}, %2;" : "=f"(lo), "=f"(hi) : "l"(a));
    return lo + hi;
}

// ============================================================
// K1: Q = [S;T] @ W[:C]^T   (M=256, N=256, K=512), fp32 via packed f32x2.
// grid = 32 row-groups x 4 col-groups = 128 blocks, 256 threads (8 warps).
// Each lane register-caches its K-chunk (16 floats = 8 f32x2) of 8 X rows.
// Warp w computes 8 columns; W row loads are coalesced 128-bit; result via
// shuffle reduce. Also zeroes d_out for K2's atomic accumulation.
// ============================================================
__global__ __launch_bounds__(256, 1)
void gemm_kernel(const float* __restrict__ sf,
                 const float* __restrict__ tf,
                 const float* __restrict__ W,
                 float* __restrict__ out) {
    if (blockIdx.x == 0 && threadIdx.x == 0) *out = 0.0f;

    const int rg   = blockIdx.x >> 2;   // 0..31
    const int cg   = blockIdx.x & 3;    // 0..3
    const int tid  = threadIdx.x;
    const int w    = tid >> 5;
    const int lane = tid & 31;
    const int row0 = rg * RG;

    // cache 8 rows: lane's floats are k = seg*128 + lane*4 + {0..3}, seg 0..3
    unsigned long long x2[RG][8];
#pragma unroll
    for (int r = 0; r < RG; r++) {
        const int row = row0 + r;
        const float* xr = (row < NS) ? (sf + row * A) : (tf + (row - NS) * A);
        const ulonglong2* xu = reinterpret_cast<const ulonglong2*>(xr);
#pragma unroll
        for (int seg = 0; seg < 4; seg++) {
            const ulonglong2 v = xu[seg * 32 + lane];
            x2[r][2 * seg + 0] = v.x;
            x2[r][2 * seg + 1] = v.y;
        }
    }

#pragma unroll
    for (int i = 0; i < 8; i++) {
        const int c = cg * 64 + w * 8 + i;
        const ulonglong2* wr = reinterpret_cast<const ulonglong2*>(W + c * A);

        unsigned long long acc[RG];
#pragma unroll
        for (int r = 0; r < RG; r++) acc[r] = 0ull;

#pragma unroll
        for (int seg = 0; seg < 4; seg++) {
            const ulonglong2 wv = wr[seg * 32 + lane];
#pragma unroll
            for (int r = 0; r < RG; r++) {
                fma2(acc[r], x2[r][2 * seg + 0], wv.x);
                fma2(acc[r], x2[r][2 * seg + 1], wv.y);
            }
        }

#pragma unroll
        for (int r = 0; r < RG; r++) {
            float s = sum2(acc[r]);
#pragma unroll
            for (int off = 16; off; off >>= 1)
                s += __shfl_down_sync(0xffffffffu, s, off);
            if (lane == 0) g_Q[(row0 + r) * C + c] = s;
        }
    }
}

// ============================================================
// K2: per-sample everything (member compaction + class agg + sigma +
// softmax + loss).  grid = 128 blocks (one per sample n), 256 threads
// (thread tid == column c).
// With t = tt[n]:
//   members_s = { m : ts[m] == t }   (cnt_s entries, typically 0-3)
//   members_t = { m : tt[m] == t }   (cnt_t >= 1, contains n itself)
//   d_mc  = Qs[m,c] - Qs[m,t]  over members_s
//   sigma = icnt*sum(d^2) - (icnt*sum(d))^2
//   x[c]  = 0.5*(mean_s Qs[m,c] + mean_t Qt[m,c]) + bias[c] + 0.25*sigma
//   loss += (lse(x) - x[t]) / NS    (atomicAdd into d_out)
// Member lists are built by smem-atomic compaction (order irrelevant: sums),
// so the accumulation loops run cnt iterations instead of 128.
// ============================================================
__global__ __launch_bounds__(256, 4)
void loss_kernel(const float* __restrict__ bias,
                 const int* __restrict__ ts,
                 const int* __restrict__ ttg,
                 float* __restrict__ out) {
    __shared__ int   list_s[NS];
    __shared__ int   list_t[NS];
    __shared__ int   cnts[2];        // [0]=cnt_s, [1]=cnt_t
    __shared__ int   t_sh;
    __shared__ float xv[C];
    __shared__ float red[8];
    __shared__ float bc;

    const int tid  = threadIdx.x;   // == column c
    const int n    = blockIdx.x;
    const int w    = tid >> 5;
    const int lane = tid & 31;

    if (tid < 2)  cnts[tid] = 0;
    if (tid == 0) t_sh = ttg[n];
    __syncthreads();
    const int t = t_sh;

    // member compaction: thread m tests its label against t
    if (tid < NS) {
        if (ts[tid] == t)  { const int p = atomicAdd(&cnts[0], 1); list_s[p] = tid; }
        if (ttg[tid] == t) { const int p = atomicAdd(&cnts[1], 1); list_t[p] = tid; }
    }
    const float b = bias[tid];       // overlap with compaction
    __syncthreads();

    const int cnt_s = cnts[0];
    const int cnt_t = cnts[1];       // >= 1 (n itself)

    // pass 1: source members (Qs rows 0..127)
    float sig = 0.f, sd = 0.f, qs = 0.f;
    for (int i = 0; i < cnt_s; i++) {
        const int m = list_s[i];
        const float qmt = g_Q[m * C + t];     // uniform -> broadcast
        const float qmc = g_Q[m * C + tid];   // coalesced
        const float d   = qmc - qmt;
        sig = fmaf(d, d, sig);
        sd += d;
        qs += qmc;
    }
    const float icnt  = 1.0f / (float)(cnt_s > 0 ? cnt_s : 1);
    const float e     = icnt * sd;
    const float sigma = icnt * sig - e * e;
    const float Us    = icnt * qs;

    // pass 2: target members (Qt rows 128..255)
    float qt = 0.f;
    for (int i = 0; i < cnt_t; i++) {
        const int m = list_t[i];
        qt += g_Q[(NS + m) * C + tid];
    }
    const float Ut = qt / (float)cnt_t;

    const float x = 0.5f * (Us + Ut) + b + 0.25f * sigma;
    xv[tid] = x;
    __syncthreads();

    // block max
    float mx = x;
#pragma unroll
    for (int off = 16; off; off >>= 1)
        mx = fmaxf(mx, __shfl_xor_sync(0xffffffffu, mx, off));
    if (lane == 0) red[w] = mx;
    __syncthreads();
    if (tid < 8) {
        float mm = red[tid];
#pragma unroll
        for (int off = 4; off; off >>= 1)
            mm = fmaxf(mm, __shfl_xor_sync(0xffu, mm, off));
        if (tid == 0) bc = mm;
    }
    __syncthreads();
    const float bmax = bc;

    // block sum of exp
    float es = __expf(x - bmax);
#pragma unroll
    for (int off = 16; off; off >>= 1)
        es += __shfl_xor_sync(0xffffffffu, es, off);
    if (lane == 0) red[w] = es;
    __syncthreads();
    if (tid < 8) {
        float ss = red[tid];
#pragma unroll
        for (int off = 4; off; off >>= 1)
            ss += __shfl_xor_sync(0xffu, ss, off);
        if (tid == 0) bc = ss;
    }
    __syncthreads();

    if (tid == 0) {
        const float lse = bmax + __logf(bc);
        atomicAdd(out, (lse - xv[t]) * (1.0f / (float)NS));
    }
}

// ============================================================
// launch
// inputs (metadata order): fc_weight(2C*A), fc_bias(2C), s_features(NS*A),
//                          t_features(NS*A), target_s(NS), target_t(NS)
// output: float scalar
// ============================================================
extern "C" void kernel_launch(void* const* d_in, const int* in_sizes, int n_in,
                              void* d_out, int out_size) {
    const float* fw = (const float*)d_in[0];
    const float* fb = (const float*)d_in[1];
    const float* sf = (const float*)d_in[2];
    const float* tf = (const float*)d_in[3];
    const int*   ts = (const int*)d_in[4];
    const int*   tt = (const int*)d_in[5];
    float* out = (float*)d_out;

    gemm_kernel<<<128, 256>>>(sf, tf, fw, out);
    loss_kernel<<<NS, 256>>>(fb, ts, tt, out);
}